// round 13
// baseline (speedup 1.0000x reference)
#include <cuda_runtime.h>
#include <cuda_fp16.h>
#include <cstdint>

// ---------------- problem constants ----------------
#define BM 128
#define BN 128
#define BK 64
#define KH 2048
#define NTOK 4096            // B*T
#define VSZ 32000
#define NVT (VSZ / BN)       // 250
#define NSLICE (NVT * 2)     // 500: each warp-n half writes its own partial
#define NIT (KH / BK)        // 32
#define NSTAGE 3
#define L2E 1.44269504f      // log2(e)
#define LN2 0.69314718056f   // 1/log2(e)

// ---------------- device scratch (no allocs allowed) ----------------
__device__ __half g_w[(size_t)VSZ * KH];           // 128 MB fp16 weights
__device__ __half g_a[(size_t)NTOK * KH];          // 16 MB fp16 acts (compacted, x L2E)
__device__ float g_psum[(size_t)NSLICE * NTOK];    // per (slice, compact-token) sumexp
__device__ float g_tgt[NTOK];                      // target logit (fp32, orig idx)
__device__ int   g_tgti[NTOK];                     // decoded target indices (orig idx)
__device__ int   g_cmap[NTOK];                     // orig -> compact (-1 if masked)
__device__ int   g_inv[NTOK];                      // compact -> orig
__device__ int   g_neff[1];                        // number of unmasked tokens
__device__ int   g_wcnt[NVT];                      // per-vtile conversion counters (0-init)
__device__ float g_avg[8];                         // per-sequence avg logp

// ---------------- smem layout ----------------
#define A_STG (BM * 128)                 // 16384 B (128 rows x 128B)
#define B_STG (BN * 128)                 // 16384 B
#define STG   (A_STG + B_STG)            // 32768 B per stage
#define SMEM_BYTES (NSTAGE * STG)        // 98304 B -> 2 CTAs/SM

// ---------------- helpers ----------------
__device__ __forceinline__ uint32_t smem_u32(const void* p) {
    uint32_t a;
    asm("{ .reg .u64 t; cvta.to.shared.u64 t, %1; cvt.u32.u64 %0, t; }" : "=r"(a) : "l"(p));
    return a;
}
__device__ __forceinline__ uint32_t sw128(uint32_t off) { return off ^ ((off >> 3) & 0x70); }

__device__ __forceinline__ void cp16(uint32_t s, const void* g) {
    asm volatile("cp.async.cg.shared.global [%0], [%1], 16;" :: "r"(s), "l"(g) : "memory");
}
__device__ __forceinline__ void cp_commit() { asm volatile("cp.async.commit_group;" ::: "memory"); }

__device__ __forceinline__ void ldsm4(uint32_t* r, uint32_t addr) {
    asm volatile("ldmatrix.sync.aligned.m8n8.x4.shared.b16 {%0,%1,%2,%3}, [%4];"
                 : "=r"(r[0]), "=r"(r[1]), "=r"(r[2]), "=r"(r[3]) : "r"(addr));
}
__device__ __forceinline__ void mma16816(float* c, const uint32_t* a, const uint32_t* b) {
    asm volatile("mma.sync.aligned.m16n8k16.row.col.f32.f16.f16.f32 "
                 "{%0,%1,%2,%3}, {%4,%5,%6,%7}, {%8,%9}, {%0,%1,%2,%3};"
                 : "+f"(c[0]), "+f"(c[1]), "+f"(c[2]), "+f"(c[3])
                 : "r"(a[0]), "r"(a[1]), "r"(a[2]), "r"(a[3]), "r"(b[0]), "r"(b[1]));
}
__device__ __forceinline__ uint32_t cvt_f16x2(float hi, float lo) {
    uint32_t p;
    asm("cvt.rn.f16x2.f32 %0, %1, %2;" : "=r"(p) : "f"(hi), "f"(lo));
    return p;
}
__device__ __forceinline__ uint32_t hadd2u(uint32_t a, uint32_t b) {
    uint32_t d;
    asm("add.rn.f16x2 %0, %1, %2;" : "=r"(d) : "r"(a), "r"(b));
    return d;
}
__device__ __forceinline__ uint32_t ex2_f16x2(uint32_t a) {
    uint32_t d;
    asm("ex2.approx.f16x2 %0, %1;" : "=r"(d) : "r"(a));
    return d;
}
__device__ __forceinline__ int ld_acq(const int* p) {
    int v;
    asm volatile("ld.global.acquire.gpu.b32 %0, [%1];" : "=r"(v) : "l"(p) : "memory");
    return v;
}

// ---------------- decode + compaction (int32/int64 detect, prefix sum) ------
__global__ void __launch_bounds__(1024) tgt_decode_kernel(const int* __restrict__ t32) {
    __shared__ int s_is64;
    __shared__ int warp_tot[32];
    if (threadIdx.x == 0) s_is64 = 1;
    __syncthreads();
    int ok64 = 1;
    #pragma unroll
    for (int j = 0; j < 4; j++) {
        const int i = threadIdx.x + j * 1024;          // probe first 4096 words (16 KB, safe)
        const int v = t32[i];
        if (i & 1) { if (v != 0 && v != -1) ok64 = 0; }
        else       { if (!(v == -100 || (v >= 0 && v < VSZ))) ok64 = 0; }
    }
    if (!ok64) s_is64 = 0;
    __syncthreads();
    const int is64 = s_is64;

    int tg[4], msk[4], cnt = 0;
    #pragma unroll
    for (int j = 0; j < 4; j++) {
        const int i = threadIdx.x * 4 + j;
        tg[j] = is64 ? t32[2 * i] : t32[i];
        msk[j] = (tg[j] != -100);
        cnt += msk[j];
    }
    const int lane = threadIdx.x & 31, wid = threadIdx.x >> 5;
    int pre = cnt;
    #pragma unroll
    for (int o = 1; o < 32; o <<= 1) {
        int v = __shfl_up_sync(0xffffffffu, pre, o);
        if (lane >= o) pre += v;
    }
    if (lane == 31) warp_tot[wid] = pre;
    __syncthreads();
    if (wid == 0) {
        int v = warp_tot[lane];
        #pragma unroll
        for (int o = 1; o < 32; o <<= 1) {
            int u = __shfl_up_sync(0xffffffffu, v, o);
            if (lane >= o) v += u;
        }
        warp_tot[lane] = v;
    }
    __syncthreads();
    int base = (wid > 0 ? warp_tot[wid - 1] : 0) + (pre - cnt);
    #pragma unroll
    for (int j = 0; j < 4; j++) {
        const int i = threadIdx.x * 4 + j;
        g_tgti[i] = tg[j];
        if (msk[j]) { g_cmap[i] = base; g_inv[base] = i; base++; }
        else        { g_cmap[i] = -1; }
    }
    if (threadIdx.x == 1023) g_neff[0] = warp_tot[31];
}

// ---------------- fp32 -> fp16 converts ----------------
__device__ __forceinline__ unsigned pk2(float lo, float hi) {
    __half2 t = __floats2half2_rn(lo, hi);
    return *reinterpret_cast<unsigned*>(&t);
}
// gather-compact + scale by log2(e): block = compact row
__global__ void __launch_bounds__(256) cvt_a_kernel(const float* __restrict__ src) {
    const int c = blockIdx.x;
    const int n = g_neff[0];
    uint4* dst = reinterpret_cast<uint4*>(g_a + (size_t)c * KH);
    if (c < n) {
        const int orig = g_inv[c];
        const float4* r4 = reinterpret_cast<const float4*>(src + (size_t)orig * KH);
        float4 a = __ldcs(&r4[2 * threadIdx.x]), b = __ldcs(&r4[2 * threadIdx.x + 1]);
        uint4 o;
        o.x = pk2(a.x * L2E, a.y * L2E); o.y = pk2(a.z * L2E, a.w * L2E);
        o.z = pk2(b.x * L2E, b.y * L2E); o.w = pk2(b.z * L2E, b.w * L2E);
        dst[threadIdx.x] = o;
    } else {
        dst[threadIdx.x] = make_uint4(0, 0, 0, 0);
    }
}

// ---------------- fused W-convert + GEMM + partial sum-exp + target ---------
// acc = log2(e) * logit_nobias (A pre-scaled by L2E).
// Each CTA (bx, vt) converts W rows [v0 + bx*4, +4) fp32->fp16, signals the
// per-vtile counter, then waits for all 32 CTAs of its vtile before loading.
__global__ void __launch_bounds__(128, 2) gemm_softmax_kernel(
    const float* __restrict__ bias, const float* __restrict__ wsrc) {
    const int tid = threadIdx.x;
    const int vt = blockIdx.y;
    const int v0 = vt * BN;

    // ---- convert my 4 W rows (48 KB read, 16 KB write), streaming ----
    {
        const int r0 = v0 + blockIdx.x * 4;            // 4 rows of this vtile
        const float4* src = reinterpret_cast<const float4*>(wsrc + (size_t)r0 * KH);
        uint4* dst = reinterpret_cast<uint4*>(g_w + (size_t)r0 * KH);
        float4 a[8], b[8];
        #pragma unroll
        for (int j = 0; j < 8; j++) {                  // 1024 uint4 / 128 thr = 8
            const int p = tid + j * 128;
            a[j] = __ldcs(&src[2 * p]);
            b[j] = __ldcs(&src[2 * p + 1]);
        }
        #pragma unroll
        for (int j = 0; j < 8; j++) {
            const int p = tid + j * 128;
            uint4 o;
            o.x = pk2(a[j].x, a[j].y); o.y = pk2(a[j].z, a[j].w);
            o.z = pk2(b[j].x, b[j].y); o.w = pk2(b[j].z, b[j].w);
            __stcs(dst + p, o);
        }
        __syncthreads();
        if (tid == 0) {
            __threadfence();
            atomicAdd(&g_wcnt[vt], 1);
        }
    }

    const int neff = g_neff[0];
    const int m0 = blockIdx.x * BM;
    if (m0 >= neff) return;                          // tile fully masked out (after signal!)

    // ---- wait for the whole vtile's W to be converted ----
    if (tid == 0) {
        while (ld_acq(&g_wcnt[vt]) < 32) { __nanosleep(64); }
    }
    __syncthreads();

    extern __shared__ char smem[];
    const uint32_t sbase = smem_u32(smem);
    const int lane = tid & 31;
    const int warp = tid >> 5;
    const int wm = warp >> 1;          // 0..1  (m slice of 64 rows)
    const int wn = warp & 1;           // 0..1  (n slice of 64 cols)

    auto load_stage = [&](int it) {
        const int st = it % NSTAGE;
        const int k0 = it * BK;
        const uint32_t sA = sbase + st * STG;
        const __half* ab = g_a + (size_t)m0 * KH + k0;
        #pragma unroll
        for (int j = 0; j < 8; j++) {
            int id = tid + j * 128;
            int row = id >> 3, seg = id & 7;
            cp16(sA + sw128(row * 128 + seg * 16), ab + (size_t)row * KH + seg * 8);
        }
        const uint32_t sB = sA + A_STG;
        const __half* bb = g_w + (size_t)v0 * KH + k0;
        #pragma unroll
        for (int j = 0; j < 8; j++) {
            int id = tid + j * 128;
            int row = id >> 3, seg = id & 7;
            cp16(sB + sw128(row * 128 + seg * 16), bb + (size_t)row * KH + seg * 8);
        }
    };

    load_stage(0); cp_commit();
    load_stage(1); cp_commit();

    float acc[4][8][4];
    #pragma unroll
    for (int mt = 0; mt < 4; mt++)
        #pragma unroll
        for (int nt = 0; nt < 8; nt++)
            #pragma unroll
            for (int r = 0; r < 4; r++) acc[mt][nt][r] = 0.f;

    uint32_t aoff[4], boff[4];
    #pragma unroll
    for (int mt = 0; mt < 4; mt++)
        aoff[mt] = (uint32_t)(wm * 64 + mt * 16 + (lane & 7) + ((lane >> 3) & 1) * 8) * 128
                 + ((lane >> 4) & 1) * 16;
    #pragma unroll
    for (int np = 0; np < 4; np++)
        boff[np] = (uint32_t)(wn * 64 + np * 16 + ((lane >> 4) & 1) * 8 + (lane & 7)) * 128
                 + ((lane >> 3) & 1) * 16;

    for (int it = 0; it < NIT; ++it) {
        asm volatile("cp.async.wait_group 1;" ::: "memory");
        __syncthreads();

        const uint32_t sA = sbase + (it % NSTAGE) * STG;
        const uint32_t sB = sA + A_STG;
        const bool do_load = (it + 2 < NIT);
        const int lst = (it + 2) % NSTAGE;
        const uint32_t dA = sbase + lst * STG;
        const uint32_t dB = dA + A_STG;
        const int lk0 = (it + 2) * BK;
        const __half* ab = g_a + (size_t)m0 * KH + lk0;
        const __half* bb = g_w + (size_t)v0 * KH + lk0;

        #pragma unroll
        for (int ks = 0; ks < 4; ks++) {
            uint32_t a[4][4], b[4][4];
            #pragma unroll
            for (int mt = 0; mt < 4; mt++) ldsm4(a[mt], sA + sw128(aoff[mt] + ks * 32));
            #pragma unroll
            for (int np = 0; np < 4; np++) ldsm4(b[np], sB + sw128(boff[np] + ks * 32));

            if (do_load) {
                #pragma unroll
                for (int j = 0; j < 4; j++) {
                    const int chunk = ks * 4 + j;       // 0..15
                    const int id = tid + (chunk & 7) * 128;
                    const int row = id >> 3, seg = id & 7;
                    if (chunk < 8)
                        cp16(dA + sw128(row * 128 + seg * 16), ab + (size_t)row * KH + seg * 8);
                    else
                        cp16(dB + sw128(row * 128 + seg * 16), bb + (size_t)row * KH + seg * 8);
                }
            }

            #pragma unroll
            for (int mt = 0; mt < 4; mt++)
                #pragma unroll
                for (int nt = 0; nt < 8; nt++)
                    mma16816(acc[mt][nt], a[mt], b[nt >> 1] + (nt & 1) * 2);
        }
        cp_commit();
    }

    // ---------------- epilogue: f16x2 exp2 partial sums + target extract ----
    asm volatile("cp.async.wait_group 0;" ::: "memory");
    __syncthreads();
    uint32_t* sbias2 = reinterpret_cast<uint32_t*>(smem);          // 64 x half2
    int* stgt = reinterpret_cast<int*>(smem) + 64;                 // 128 x tgt col
    if (tid < 64) {
        __half2 h = __floats2half2_rn(bias[v0 + 2 * tid] * L2E,
                                      bias[v0 + 2 * tid + 1] * L2E);
        sbias2[tid] = *reinterpret_cast<uint32_t*>(&h);
    }
    {
        const int r = m0 + tid;
        stgt[tid] = (r < neff) ? (g_tgti[g_inv[r]] - v0) : 0x40000000;
    }
    __syncthreads();

    const int slice = vt * 2 + wn;
    const int pbase = wn * 32 + (lane & 3);          // half2 pair index of nt=0
    const int cbase = wn * 64 + (lane & 3) * 2;      // local col of reg j=0

    #pragma unroll
    for (int mt = 0; mt < 4; mt++) {
        #pragma unroll
        for (int half = 0; half < 2; half++) {
            const int row = wm * 64 + mt * 16 + (lane >> 2) + half * 8;
            const int ctok = m0 + row;               // compact token index
            uint32_t hs = 0;                         // half2 accumulator
            #pragma unroll
            for (int nt = 0; nt < 8; nt++) {
                uint32_t p = cvt_f16x2(acc[mt][nt][2 * half + 1], acc[mt][nt][2 * half]);
                p = hadd2u(p, sbias2[pbase + nt * 4]);
                hs = hadd2u(hs, ex2_f16x2(p));
            }
            const __half2 h = *reinterpret_cast<__half2*>(&hs);
            float S = __low2float(h) + __high2float(h);
            S += __shfl_xor_sync(0xffffffffu, S, 1);
            S += __shfl_xor_sync(0xffffffffu, S, 2);
            if ((lane & 3) == 0)
                g_psum[(size_t)slice * NTOK + ctok] = S;

            // target logit extraction via smem-cached column (rarely matches)
            const int tl = stgt[row] - cbase;
            if ((unsigned)tl < 58u) {                // only cols cbase..cbase+57 reachable
                #pragma unroll
                for (int nt = 0; nt < 8; nt++) {
                    if (tl == nt * 8)
                        g_tgt[g_inv[ctok]] = fmaf(acc[mt][nt][2 * half], LN2,
                                                  __ldg(&bias[v0 + cbase + nt * 8]));
                    if (tl == nt * 8 + 1)
                        g_tgt[g_inv[ctok]] = fmaf(acc[mt][nt][2 * half + 1], LN2,
                                                  __ldg(&bias[v0 + cbase + nt * 8 + 1]));
                }
            }
        }
    }
}

// ---------------- per-sequence logp combine + avg ----------------
__global__ void reduce_kernel() {
    __shared__ float rs[512];
    __shared__ float rc[512];
    const int seq = blockIdx.x, t = threadIdx.x;
    const int token = seq * 512 + t;
    const int tg = g_tgti[token];
    float val = 0.f, cnt = 0.f;
    if (tg != -100) {
        const int c = g_cmap[token];
        float S = 0.f;
        #pragma unroll 4
        for (int sl = 0; sl < NSLICE; sl++)
            S += g_psum[(size_t)sl * NTOK + c];
        val = g_tgt[token] - __logf(S);
        cnt = 1.f;
    }
    rs[t] = val; rc[t] = cnt;
    __syncthreads();
    for (int o = 256; o > 0; o >>= 1) {
        if (t < o) { rs[t] += rs[t + o]; rc[t] += rc[t + o]; }
        __syncthreads();
    }
    if (t == 0) g_avg[seq] = rs[0] / fmaxf(rc[0], 1.f);
}

// ---------------- SimPO pair loss + counter reset for next replay ----------
__global__ void finalize_kernel(float* __restrict__ out) {
    // reset per-vtile conversion counters (graph replays reuse them)
    for (int i = threadIdx.x; i < NVT; i += 32) g_wcnt[i] = 0;
    if (threadIdx.x == 0 && blockIdx.x == 0) {
        float loss = 0.f;
        #pragma unroll
        for (int i = 0; i < 4; i++) {
            const float d = 0.1f * (g_avg[i] - g_avg[i + 4]) - 0.5f;
            const float xm = -d;  // -log_sigmoid(d) = softplus(-d)
            loss += (xm > 0.f) ? (xm + log1pf(expf(-xm))) : log1pf(expf(xm));
        }
        out[0] = loss * 0.25f;
    }
}

// ---------------- launch ----------------
extern "C" void kernel_launch(void* const* d_in, const int* in_sizes, int n_in,
                              void* d_out, int out_size) {
    const float* lin_weight = (const float*)d_in[0];       // [V, H]
    const float* input      = (const float*)d_in[1];       // [B, T, H]
    const int*   target_raw = (const int*)d_in[2];         // [B, T] int32 or int64
    const float* bias       = (const float*)d_in[3];       // [V]

    cudaFuncSetAttribute(gemm_softmax_kernel,
                         cudaFuncAttributeMaxDynamicSharedMemorySize, SMEM_BYTES);

    tgt_decode_kernel<<<1, 1024>>>(target_raw);
    cvt_a_kernel<<<NTOK, 256>>>(input);

    dim3 grid(NTOK / BM, NVT);   // x-fastest => M-CTAs share each W tile in L2
    gemm_softmax_kernel<<<grid, 128, SMEM_BYTES>>>(bias, lin_weight);

    reduce_kernel<<<8, 512>>>();
    finalize_kernel<<<1, 32>>>((float*)d_out);
}

// round 14
// speedup vs baseline: 1.0525x; 1.0525x over previous
#include <cuda_runtime.h>
#include <cuda_fp16.h>
#include <cstdint>

// ---------------- problem constants ----------------
#define BM 128
#define BN 128
#define BK 64
#define KH 2048
#define NTOK 4096            // B*T
#define VSZ 32000
#define NVT (VSZ / BN)       // 250
#define NSLICE (NVT * 2)     // 500: each warp-n half writes its own partial
#define NIT (KH / BK)        // 32
#define NSTAGE 3
#define L2E 1.44269504f      // log2(e)
#define LN2 0.69314718056f   // 1/log2(e)

// ---------------- device scratch (no allocs allowed) ----------------
__device__ __half g_w[(size_t)VSZ * KH];           // 128 MB fp16 weights
__device__ __half g_a[(size_t)NTOK * KH];          // 16 MB fp16 acts (compacted, x L2E)
__device__ float g_psum[(size_t)NSLICE * NTOK];    // per (slice, compact-token) sumexp
__device__ float g_tgt[NTOK];                      // target logit (fp32, orig idx)
__device__ float g_logp[NTOK];                     // per-token logp (orig idx)
__device__ int   g_tgti[NTOK];                     // decoded target indices (orig idx)
__device__ int   g_cmap[NTOK];                     // orig -> compact (-1 if masked)
__device__ int   g_inv[NTOK];                      // compact -> orig
__device__ int   g_neff[1];                        // number of unmasked tokens
__device__ float g_avg[8];                         // per-sequence avg logp

// ---------------- smem layout ----------------
#define A_STG (BM * 128)                 // 16384 B (128 rows x 128B)
#define B_STG (BN * 128)                 // 16384 B
#define STG   (A_STG + B_STG)            // 32768 B per stage
#define SMEM_BYTES (NSTAGE * STG)        // 98304 B -> 2 CTAs/SM

// ---------------- helpers ----------------
__device__ __forceinline__ uint32_t smem_u32(const void* p) {
    uint32_t a;
    asm("{ .reg .u64 t; cvta.to.shared.u64 t, %1; cvt.u32.u64 %0, t; }" : "=r"(a) : "l"(p));
    return a;
}
__device__ __forceinline__ uint32_t sw128(uint32_t off) { return off ^ ((off >> 3) & 0x70); }

__device__ __forceinline__ void cp16(uint32_t s, const void* g) {
    asm volatile("cp.async.cg.shared.global [%0], [%1], 16;" :: "r"(s), "l"(g) : "memory");
}
__device__ __forceinline__ void cp_commit() { asm volatile("cp.async.commit_group;" ::: "memory"); }

__device__ __forceinline__ void ldsm4(uint32_t* r, uint32_t addr) {
    asm volatile("ldmatrix.sync.aligned.m8n8.x4.shared.b16 {%0,%1,%2,%3}, [%4];"
                 : "=r"(r[0]), "=r"(r[1]), "=r"(r[2]), "=r"(r[3]) : "r"(addr));
}
__device__ __forceinline__ void mma16816(float* c, const uint32_t* a, const uint32_t* b) {
    asm volatile("mma.sync.aligned.m16n8k16.row.col.f32.f16.f16.f32 "
                 "{%0,%1,%2,%3}, {%4,%5,%6,%7}, {%8,%9}, {%0,%1,%2,%3};"
                 : "+f"(c[0]), "+f"(c[1]), "+f"(c[2]), "+f"(c[3])
                 : "r"(a[0]), "r"(a[1]), "r"(a[2]), "r"(a[3]), "r"(b[0]), "r"(b[1]));
}
__device__ __forceinline__ uint32_t cvt_f16x2(float hi, float lo) {
    uint32_t p;
    asm("cvt.rn.f16x2.f32 %0, %1, %2;" : "=r"(p) : "f"(hi), "f"(lo));
    return p;
}
__device__ __forceinline__ uint32_t hadd2u(uint32_t a, uint32_t b) {
    uint32_t d;
    asm("add.rn.f16x2 %0, %1, %2;" : "=r"(d) : "r"(a), "r"(b));
    return d;
}
__device__ __forceinline__ uint32_t ex2_f16x2(uint32_t a) {
    uint32_t d;
    asm("ex2.approx.f16x2 %0, %1;" : "=r"(d) : "r"(a));
    return d;
}

// ---------------- decode + compaction (int32/int64 detect, prefix sum) ------
__global__ void __launch_bounds__(1024) tgt_decode_kernel(const int* __restrict__ t32) {
    __shared__ int s_is64;
    __shared__ int warp_tot[32];
    if (threadIdx.x == 0) s_is64 = 1;
    __syncthreads();
    int ok64 = 1;
    #pragma unroll
    for (int j = 0; j < 4; j++) {
        const int i = threadIdx.x + j * 1024;          // probe first 4096 words (16 KB, safe)
        const int v = t32[i];
        if (i & 1) { if (v != 0 && v != -1) ok64 = 0; }
        else       { if (!(v == -100 || (v >= 0 && v < VSZ))) ok64 = 0; }
    }
    if (!ok64) s_is64 = 0;
    __syncthreads();
    const int is64 = s_is64;

    int tg[4], msk[4], cnt = 0;
    #pragma unroll
    for (int j = 0; j < 4; j++) {
        const int i = threadIdx.x * 4 + j;
        tg[j] = is64 ? t32[2 * i] : t32[i];
        msk[j] = (tg[j] != -100);
        cnt += msk[j];
    }
    const int lane = threadIdx.x & 31, wid = threadIdx.x >> 5;
    int pre = cnt;
    #pragma unroll
    for (int o = 1; o < 32; o <<= 1) {
        int v = __shfl_up_sync(0xffffffffu, pre, o);
        if (lane >= o) pre += v;
    }
    if (lane == 31) warp_tot[wid] = pre;
    __syncthreads();
    if (wid == 0) {
        int v = warp_tot[lane];
        #pragma unroll
        for (int o = 1; o < 32; o <<= 1) {
            int u = __shfl_up_sync(0xffffffffu, v, o);
            if (lane >= o) v += u;
        }
        warp_tot[lane] = v;
    }
    __syncthreads();
    int base = (wid > 0 ? warp_tot[wid - 1] : 0) + (pre - cnt);
    #pragma unroll
    for (int j = 0; j < 4; j++) {
        const int i = threadIdx.x * 4 + j;
        g_tgti[i] = tg[j];
        if (msk[j]) { g_cmap[i] = base; g_inv[base] = i; base++; }
        else        { g_cmap[i] = -1; }
    }
    if (threadIdx.x == 1023) g_neff[0] = warp_tot[31];
}

// ---------------- fp32 -> fp16 converts ----------------
__device__ __forceinline__ unsigned pk2(float lo, float hi) {
    __half2 t = __floats2half2_rn(lo, hi);
    return *reinterpret_cast<unsigned*>(&t);
}
// 4 float4-pairs per thread, streaming in + streaming out. 8000 blocks x 256.
__global__ void __launch_bounds__(256) cvt_w_kernel(const float4* __restrict__ src) {
    const int p0 = blockIdx.x * 1024 + threadIdx.x;    // uint4 output index base
    float4 a[4], b[4];
    #pragma unroll
    for (int j = 0; j < 4; j++) {
        const int p = p0 + j * 256;
        a[j] = __ldcs(&src[2 * p]);
        b[j] = __ldcs(&src[2 * p + 1]);
    }
    #pragma unroll
    for (int j = 0; j < 4; j++) {
        const int p = p0 + j * 256;
        uint4 o;
        o.x = pk2(a[j].x, a[j].y); o.y = pk2(a[j].z, a[j].w);
        o.z = pk2(b[j].x, b[j].y); o.w = pk2(b[j].z, b[j].w);
        __stcs(reinterpret_cast<uint4*>(g_w) + p, o);
    }
}
// gather-compact + scale by log2(e): block = compact row
__global__ void __launch_bounds__(256) cvt_a_kernel(const float* __restrict__ src) {
    const int c = blockIdx.x;
    const int n = g_neff[0];
    uint4* dst = reinterpret_cast<uint4*>(g_a + (size_t)c * KH);
    if (c < n) {
        const int orig = g_inv[c];
        const float4* r4 = reinterpret_cast<const float4*>(src + (size_t)orig * KH);
        float4 a = __ldcs(&r4[2 * threadIdx.x]), b = __ldcs(&r4[2 * threadIdx.x + 1]);
        uint4 o;
        o.x = pk2(a.x * L2E, a.y * L2E); o.y = pk2(a.z * L2E, a.w * L2E);
        o.z = pk2(b.x * L2E, b.y * L2E); o.w = pk2(b.z * L2E, b.w * L2E);
        dst[threadIdx.x] = o;
    } else {
        dst[threadIdx.x] = make_uint4(0, 0, 0, 0);
    }
}

// ---------------- fused GEMM + partial sum-exp + target extraction ----------
// acc = log2(e) * logit_nobias (A pre-scaled by L2E).
__global__ void __launch_bounds__(128, 2) gemm_softmax_kernel(
    const float* __restrict__ bias) {
    const int neff = g_neff[0];
    const int m0 = blockIdx.x * BM;
    if (m0 >= neff) return;                          // tile fully masked out
    extern __shared__ char smem[];
    const uint32_t sbase = smem_u32(smem);
    const int tid = threadIdx.x;
    const int lane = tid & 31;
    const int warp = tid >> 5;
    const int wm = warp >> 1;          // 0..1  (m slice of 64 rows)
    const int wn = warp & 1;           // 0..1  (n slice of 64 cols)
    const int v0 = blockIdx.y * BN;

    auto load_stage = [&](int it) {
        const int st = it % NSTAGE;
        const int k0 = it * BK;
        const uint32_t sA = sbase + st * STG;
        const __half* ab = g_a + (size_t)m0 * KH + k0;
        #pragma unroll
        for (int j = 0; j < 8; j++) {
            int id = tid + j * 128;
            int row = id >> 3, seg = id & 7;
            cp16(sA + sw128(row * 128 + seg * 16), ab + (size_t)row * KH + seg * 8);
        }
        const uint32_t sB = sA + A_STG;
        const __half* bb = g_w + (size_t)v0 * KH + k0;
        #pragma unroll
        for (int j = 0; j < 8; j++) {
            int id = tid + j * 128;
            int row = id >> 3, seg = id & 7;
            cp16(sB + sw128(row * 128 + seg * 16), bb + (size_t)row * KH + seg * 8);
        }
    };

    load_stage(0); cp_commit();
    load_stage(1); cp_commit();

    float acc[4][8][4];
    #pragma unroll
    for (int mt = 0; mt < 4; mt++)
        #pragma unroll
        for (int nt = 0; nt < 8; nt++)
            #pragma unroll
            for (int r = 0; r < 4; r++) acc[mt][nt][r] = 0.f;

    uint32_t aoff[4], boff[4];
    #pragma unroll
    for (int mt = 0; mt < 4; mt++)
        aoff[mt] = (uint32_t)(wm * 64 + mt * 16 + (lane & 7) + ((lane >> 3) & 1) * 8) * 128
                 + ((lane >> 4) & 1) * 16;
    #pragma unroll
    for (int np = 0; np < 4; np++)
        boff[np] = (uint32_t)(wn * 64 + np * 16 + ((lane >> 4) & 1) * 8 + (lane & 7)) * 128
                 + ((lane >> 3) & 1) * 16;

    for (int it = 0; it < NIT; ++it) {
        asm volatile("cp.async.wait_group 1;" ::: "memory");
        __syncthreads();

        const uint32_t sA = sbase + (it % NSTAGE) * STG;
        const uint32_t sB = sA + A_STG;
        const bool do_load = (it + 2 < NIT);
        const int lst = (it + 2) % NSTAGE;
        const uint32_t dA = sbase + lst * STG;
        const uint32_t dB = dA + A_STG;
        const int lk0 = (it + 2) * BK;
        const __half* ab = g_a + (size_t)m0 * KH + lk0;
        const __half* bb = g_w + (size_t)v0 * KH + lk0;

        #pragma unroll
        for (int ks = 0; ks < 4; ks++) {
            uint32_t a[4][4], b[4][4];
            #pragma unroll
            for (int mt = 0; mt < 4; mt++) ldsm4(a[mt], sA + sw128(aoff[mt] + ks * 32));
            #pragma unroll
            for (int np = 0; np < 4; np++) ldsm4(b[np], sB + sw128(boff[np] + ks * 32));

            if (do_load) {
                #pragma unroll
                for (int j = 0; j < 4; j++) {
                    const int chunk = ks * 4 + j;       // 0..15
                    const int id = tid + (chunk & 7) * 128;
                    const int row = id >> 3, seg = id & 7;
                    if (chunk < 8)
                        cp16(dA + sw128(row * 128 + seg * 16), ab + (size_t)row * KH + seg * 8);
                    else
                        cp16(dB + sw128(row * 128 + seg * 16), bb + (size_t)row * KH + seg * 8);
                }
            }

            #pragma unroll
            for (int mt = 0; mt < 4; mt++)
                #pragma unroll
                for (int nt = 0; nt < 8; nt++)
                    mma16816(acc[mt][nt], a[mt], b[nt >> 1] + (nt & 1) * 2);
        }
        cp_commit();
    }

    // ---------------- epilogue: f16x2 exp2 partial sums + target extract ----
    asm volatile("cp.async.wait_group 0;" ::: "memory");
    __syncthreads();
    uint32_t* sbias2 = reinterpret_cast<uint32_t*>(smem);          // 64 x half2
    int* stgt = reinterpret_cast<int*>(smem) + 64;                 // 128 x tgt col
    if (tid < 64) {
        __half2 h = __floats2half2_rn(bias[v0 + 2 * tid] * L2E,
                                      bias[v0 + 2 * tid + 1] * L2E);
        sbias2[tid] = *reinterpret_cast<uint32_t*>(&h);
    }
    {
        const int r = m0 + tid;
        stgt[tid] = (r < neff) ? (g_tgti[g_inv[r]] - v0) : 0x40000000;
    }
    __syncthreads();

    const int slice = blockIdx.y * 2 + wn;
    const int pbase = wn * 32 + (lane & 3);          // half2 pair index of nt=0
    const int cbase = wn * 64 + (lane & 3) * 2;      // local col of reg j=0

    #pragma unroll
    for (int mt = 0; mt < 4; mt++) {
        #pragma unroll
        for (int half = 0; half < 2; half++) {
            const int row = wm * 64 + mt * 16 + (lane >> 2) + half * 8;
            const int ctok = m0 + row;               // compact token index
            uint32_t hs = 0;                         // half2 accumulator
            #pragma unroll
            for (int nt = 0; nt < 8; nt++) {
                uint32_t p = cvt_f16x2(acc[mt][nt][2 * half + 1], acc[mt][nt][2 * half]);
                p = hadd2u(p, sbias2[pbase + nt * 4]);
                hs = hadd2u(hs, ex2_f16x2(p));
            }
            const __half2 h = *reinterpret_cast<__half2*>(&hs);
            float S = __low2float(h) + __high2float(h);
            S += __shfl_xor_sync(0xffffffffu, S, 1);
            S += __shfl_xor_sync(0xffffffffu, S, 2);
            if ((lane & 3) == 0)
                g_psum[(size_t)slice * NTOK + ctok] = S;

            // target logit extraction via smem-cached column (rarely matches)
            const int tl = stgt[row] - cbase;
            if ((unsigned)tl < 58u) {                // only cols cbase..cbase+57 reachable
                #pragma unroll
                for (int nt = 0; nt < 8; nt++) {
                    if (tl == nt * 8)
                        g_tgt[g_inv[ctok]] = fmaf(acc[mt][nt][2 * half], LN2,
                                                  __ldg(&bias[v0 + cbase + nt * 8]));
                    if (tl == nt * 8 + 1)
                        g_tgt[g_inv[ctok]] = fmaf(acc[mt][nt][2 * half + 1], LN2,
                                                  __ldg(&bias[v0 + cbase + nt * 8 + 1]));
                }
            }
        }
    }
}

// ---------------- per-token combine: one warp per token --------------------
// 128 blocks x 512 threads = 2048 warps; each warp handles 2 tokens.
__global__ void __launch_bounds__(512) combine_kernel() {
    const int lane = threadIdx.x & 31;
    const int gwarp = blockIdx.x * 16 + (threadIdx.x >> 5);   // 0..2047
    #pragma unroll
    for (int half = 0; half < 2; half++) {
        const int token = gwarp + half * 2048;
        const int tg = g_tgti[token];
        float logp = 0.f;
        if (tg != -100) {
            const int c = g_cmap[token];
            float S = 0.f;
            const float* p = g_psum + c;
            #pragma unroll
            for (int k = 0; k < 16; k++) {           // 500 slices: lane + k*32 < 500
                const int sl = lane + k * 32;
                if (sl < NSLICE) S += p[(size_t)sl * NTOK];
            }
            #pragma unroll
            for (int o = 16; o > 0; o >>= 1) S += __shfl_xor_sync(0xffffffffu, S, o);
            logp = g_tgt[token] - __logf(S);
        }
        if (lane == 0) g_logp[token] = logp;
    }
}

// ---------------- per-sequence avg ----------------
__global__ void reduce_kernel() {
    __shared__ float rs[512];
    __shared__ float rc[512];
    const int seq = blockIdx.x, t = threadIdx.x;
    const int token = seq * 512 + t;
    const int masked = (g_tgti[token] == -100);
    rs[t] = masked ? 0.f : g_logp[token];
    rc[t] = masked ? 0.f : 1.f;
    __syncthreads();
    for (int o = 256; o > 0; o >>= 1) {
        if (t < o) { rs[t] += rs[t + o]; rc[t] += rc[t + o]; }
        __syncthreads();
    }
    if (t == 0) g_avg[seq] = rs[0] / fmaxf(rc[0], 1.f);
}

// ---------------- SimPO pair loss ----------------
__global__ void finalize_kernel(float* __restrict__ out) {
    if (threadIdx.x == 0 && blockIdx.x == 0) {
        float loss = 0.f;
        #pragma unroll
        for (int i = 0; i < 4; i++) {
            const float d = 0.1f * (g_avg[i] - g_avg[i + 4]) - 0.5f;
            const float xm = -d;  // -log_sigmoid(d) = softplus(-d)
            loss += (xm > 0.f) ? (xm + log1pf(expf(-xm))) : log1pf(expf(xm));
        }
        out[0] = loss * 0.25f;
    }
}

// ---------------- launch ----------------
extern "C" void kernel_launch(void* const* d_in, const int* in_sizes, int n_in,
                              void* d_out, int out_size) {
    const float* lin_weight = (const float*)d_in[0];       // [V, H]
    const float* input      = (const float*)d_in[1];       // [B, T, H]
    const int*   target_raw = (const int*)d_in[2];         // [B, T] int32 or int64
    const float* bias       = (const float*)d_in[3];       // [V]

    cudaFuncSetAttribute(gemm_softmax_kernel,
                         cudaFuncAttributeMaxDynamicSharedMemorySize, SMEM_BYTES);

    tgt_decode_kernel<<<1, 1024>>>(target_raw);
    cvt_w_kernel<<<8000, 256>>>((const float4*)lin_weight);
    cvt_a_kernel<<<NTOK, 256>>>(input);

    dim3 grid(NTOK / BM, NVT);   // x-fastest => M-CTAs share each W tile in L2
    gemm_softmax_kernel<<<grid, 128, SMEM_BYTES>>>(bias);

    combine_kernel<<<128, 512>>>();
    reduce_kernel<<<8, 512>>>();
    finalize_kernel<<<1, 32>>>((float*)d_out);
}

// round 16
// speedup vs baseline: 1.0685x; 1.0151x over previous
#include <cuda_runtime.h>
#include <cuda_fp16.h>
#include <cstdint>

// ---------------- problem constants ----------------
#define BM 128
#define BN 128
#define BK 64
#define KH 2048
#define NTOK 4096            // B*T
#define VSZ 32000
#define NVT (VSZ / BN)       // 250
#define NSLICE (NVT * 2)     // 500: each warp-n half writes its own partial
#define NIT (KH / BK)        // 32
#define NSTAGE 3
#define LOOKAHEAD 20         // vtile conversion lookahead (640 bids ~ 2+ waves)
#define L2E 1.44269504f      // log2(e)
#define LN2 0.69314718056f   // 1/log2(e)

// ---------------- device scratch (no allocs allowed) ----------------
__device__ __half g_w[(size_t)VSZ * KH];           // 128 MB fp16 weights
__device__ __half g_a[(size_t)NTOK * KH];          // 16 MB fp16 acts (compacted, x L2E)
__device__ float g_psum[(size_t)NSLICE * NTOK];    // per (slice, compact-token) sumexp
__device__ float g_tgt[NTOK];                      // target logit (fp32, orig idx)
__device__ float g_logp[NTOK];                     // per-token logp (orig idx)
__device__ int   g_tgti[NTOK];                     // decoded target indices (orig idx)
__device__ int   g_cmap[NTOK];                     // orig -> compact (-1 if masked)
__device__ int   g_inv[NTOK];                      // compact -> orig
__device__ int   g_neff[1];                        // number of unmasked tokens
__device__ int   g_wcnt[NVT];                      // per-vtile conversion counters (0-init)
__device__ float g_avg[8];                         // per-sequence avg logp

// ---------------- smem layout ----------------
#define A_STG (BM * 128)                 // 16384 B (128 rows x 128B)
#define B_STG (BN * 128)                 // 16384 B
#define STG   (A_STG + B_STG)            // 32768 B per stage
#define SMEM_BYTES (NSTAGE * STG)        // 98304 B -> 2 CTAs/SM

// ---------------- helpers ----------------
__device__ __forceinline__ uint32_t smem_u32(const void* p) {
    uint32_t a;
    asm("{ .reg .u64 t; cvta.to.shared.u64 t, %1; cvt.u32.u64 %0, t; }" : "=r"(a) : "l"(p));
    return a;
}
__device__ __forceinline__ uint32_t sw128(uint32_t off) { return off ^ ((off >> 3) & 0x70); }

__device__ __forceinline__ void cp16(uint32_t s, const void* g) {
    asm volatile("cp.async.cg.shared.global [%0], [%1], 16;" :: "r"(s), "l"(g) : "memory");
}
__device__ __forceinline__ void cp_commit() { asm volatile("cp.async.commit_group;" ::: "memory"); }

__device__ __forceinline__ void ldsm4(uint32_t* r, uint32_t addr) {
    asm volatile("ldmatrix.sync.aligned.m8n8.x4.shared.b16 {%0,%1,%2,%3}, [%4];"
                 : "=r"(r[0]), "=r"(r[1]), "=r"(r[2]), "=r"(r[3]) : "r"(addr));
}
__device__ __forceinline__ void mma16816(float* c, const uint32_t* a, const uint32_t* b) {
    asm volatile("mma.sync.aligned.m16n8k16.row.col.f32.f16.f16.f32 "
                 "{%0,%1,%2,%3}, {%4,%5,%6,%7}, {%8,%9}, {%0,%1,%2,%3};"
                 : "+f"(c[0]), "+f"(c[1]), "+f"(c[2]), "+f"(c[3])
                 : "r"(a[0]), "r"(a[1]), "r"(a[2]), "r"(a[3]), "r"(b[0]), "r"(b[1]));
}
__device__ __forceinline__ uint32_t cvt_f16x2(float hi, float lo) {
    uint32_t p;
    asm("cvt.rn.f16x2.f32 %0, %1, %2;" : "=r"(p) : "f"(hi), "f"(lo));
    return p;
}
__device__ __forceinline__ uint32_t hadd2u(uint32_t a, uint32_t b) {
    uint32_t d;
    asm("add.rn.f16x2 %0, %1, %2;" : "=r"(d) : "r"(a), "r"(b));
    return d;
}
__device__ __forceinline__ uint32_t ex2_f16x2(uint32_t a) {
    uint32_t d;
    asm("ex2.approx.f16x2 %0, %1;" : "=r"(d) : "r"(a));
    return d;
}
__device__ __forceinline__ int ld_acq(const int* p) {
    int v;
    asm volatile("ld.global.acquire.gpu.b32 %0, [%1];" : "=r"(v) : "l"(p) : "memory");
    return v;
}

// ---------------- decode + compaction (int32/int64 detect, prefix sum) ------
__global__ void __launch_bounds__(1024) tgt_decode_kernel(const int* __restrict__ t32) {
    __shared__ int s_is64;
    __shared__ int warp_tot[32];
    if (threadIdx.x == 0) s_is64 = 1;
    __syncthreads();
    int ok64 = 1;
    #pragma unroll
    for (int j = 0; j < 4; j++) {
        const int i = threadIdx.x + j * 1024;          // probe first 4096 words (16 KB, safe)
        const int v = t32[i];
        if (i & 1) { if (v != 0 && v != -1) ok64 = 0; }
        else       { if (!(v == -100 || (v >= 0 && v < VSZ))) ok64 = 0; }
    }
    if (!ok64) s_is64 = 0;
    __syncthreads();
    const int is64 = s_is64;

    int tg[4], msk[4], cnt = 0;
    #pragma unroll
    for (int j = 0; j < 4; j++) {
        const int i = threadIdx.x * 4 + j;
        tg[j] = is64 ? t32[2 * i] : t32[i];
        msk[j] = (tg[j] != -100);
        cnt += msk[j];
    }
    const int lane = threadIdx.x & 31, wid = threadIdx.x >> 5;
    int pre = cnt;
    #pragma unroll
    for (int o = 1; o < 32; o <<= 1) {
        int v = __shfl_up_sync(0xffffffffu, pre, o);
        if (lane >= o) pre += v;
    }
    if (lane == 31) warp_tot[wid] = pre;
    __syncthreads();
    if (wid == 0) {
        int v = warp_tot[lane];
        #pragma unroll
        for (int o = 1; o < 32; o <<= 1) {
            int u = __shfl_up_sync(0xffffffffu, v, o);
            if (lane >= o) v += u;
        }
        warp_tot[lane] = v;
    }
    __syncthreads();
    int base = (wid > 0 ? warp_tot[wid - 1] : 0) + (pre - cnt);
    #pragma unroll
    for (int j = 0; j < 4; j++) {
        const int i = threadIdx.x * 4 + j;
        g_tgti[i] = tg[j];
        if (msk[j]) { g_cmap[i] = base; g_inv[base] = i; base++; }
        else        { g_cmap[i] = -1; }
    }
    if (threadIdx.x == 1023) g_neff[0] = warp_tot[31];
}

// ---------------- fp32 -> fp16 converts ----------------
__device__ __forceinline__ unsigned pk2(float lo, float hi) {
    __half2 t = __floats2half2_rn(lo, hi);
    return *reinterpret_cast<unsigned*>(&t);
}
// pre-convert first LOOKAHEAD vtiles (rows 0..2559): 640 blocks x 256 thr.
__global__ void __launch_bounds__(256) cvt_w_pre_kernel(const float4* __restrict__ src) {
    const int p0 = blockIdx.x * 1024 + threadIdx.x;    // uint4 output index base
    float4 a[4], b[4];
    #pragma unroll
    for (int j = 0; j < 4; j++) {
        const int p = p0 + j * 256;
        a[j] = __ldcs(&src[2 * p]);
        b[j] = __ldcs(&src[2 * p + 1]);
    }
    #pragma unroll
    for (int j = 0; j < 4; j++) {
        const int p = p0 + j * 256;
        uint4 o;
        o.x = pk2(a[j].x, a[j].y); o.y = pk2(a[j].z, a[j].w);
        o.z = pk2(b[j].x, b[j].y); o.w = pk2(b[j].z, b[j].w);
        __stcs(reinterpret_cast<uint4*>(g_w) + p, o);
    }
}
// gather-compact + scale by log2(e): block = compact row
__global__ void __launch_bounds__(256) cvt_a_kernel(const float* __restrict__ src) {
    const int c = blockIdx.x;
    const int n = g_neff[0];
    uint4* dst = reinterpret_cast<uint4*>(g_a + (size_t)c * KH);
    if (c < n) {
        const int orig = g_inv[c];
        const float4* r4 = reinterpret_cast<const float4*>(src + (size_t)orig * KH);
        float4 a = __ldcs(&r4[2 * threadIdx.x]), b = __ldcs(&r4[2 * threadIdx.x + 1]);
        uint4 o;
        o.x = pk2(a.x * L2E, a.y * L2E); o.y = pk2(a.z * L2E, a.w * L2E);
        o.z = pk2(b.x * L2E, b.y * L2E); o.w = pk2(b.z * L2E, b.w * L2E);
        dst[threadIdx.x] = o;
    } else {
        dst[threadIdx.x] = make_uint4(0, 0, 0, 0);
    }
}

// convert 4 W rows of vtile cvt_vt (rows cvt_vt*128 + bx*4 .. +4) fp32->fp16
__device__ __forceinline__ void convert_rows(const float4* wsrc, int cvt_vt,
                                             int bx, int tid) {
    const int r0 = cvt_vt * BN + bx * 4;
    const float4* src = wsrc + (size_t)r0 * (KH / 4);
    uint4* dst = reinterpret_cast<uint4*>(g_w + (size_t)r0 * KH);
    #pragma unroll
    for (int batch = 0; batch < 2; batch++) {
        float4 a[4], b[4];
        #pragma unroll
        for (int j = 0; j < 4; j++) {
            const int p = tid + (batch * 4 + j) * 128;
            a[j] = __ldcs(&src[2 * p]);
            b[j] = __ldcs(&src[2 * p + 1]);
        }
        #pragma unroll
        for (int j = 0; j < 4; j++) {
            const int p = tid + (batch * 4 + j) * 128;
            uint4 o;
            o.x = pk2(a[j].x, a[j].y); o.y = pk2(a[j].z, a[j].w);
            o.z = pk2(b[j].x, b[j].y); o.w = pk2(b[j].z, b[j].w);
            __stcs(dst + p, o);
        }
    }
}

// ---------------- fused GEMM + partial sum-exp + target + W-pipeline --------
// acc = log2(e) * logit_nobias (A pre-scaled by L2E).
// Block (bx, vt): waits for vtile vt's W (converted by blocks of vt-LOOKAHEAD),
// runs GEMM+softmax, then converts 4 rows of vtile vt+LOOKAHEAD in its epilogue.
__global__ void __launch_bounds__(128, 2) gemm_softmax_kernel(
    const float* __restrict__ bias, const float* __restrict__ wsrc) {
    const int neff = g_neff[0];
    const int m0 = blockIdx.x * BM;
    const int vt = blockIdx.y;
    const int v0 = vt * BN;
    const int cvt_vt = vt + LOOKAHEAD;
    const int tid = threadIdx.x;
    const float4* wsrc4 = reinterpret_cast<const float4*>(wsrc);

    if (m0 >= neff) {                                // masked tile: convert + signal + exit
        if (cvt_vt < NVT) {
            convert_rows(wsrc4, cvt_vt, blockIdx.x, tid);
            __syncthreads();
            if (tid == 0) { __threadfence(); atomicAdd(&g_wcnt[cvt_vt], 1); }
        }
        return;
    }

    // wait until this vtile's W is fully converted (producers are 640 bids ahead)
    if (vt >= LOOKAHEAD) {
        if (tid == 0) {
            while (ld_acq(&g_wcnt[vt]) < 32) { __nanosleep(32); }
        }
        __syncthreads();
    }

    extern __shared__ char smem[];
    const uint32_t sbase = smem_u32(smem);
    const int lane = tid & 31;
    const int warp = tid >> 5;
    const int wm = warp >> 1;          // 0..1  (m slice of 64 rows)
    const int wn = warp & 1;           // 0..1  (n slice of 64 cols)

    auto load_stage = [&](int it) {
        const int st = it % NSTAGE;
        const int k0 = it * BK;
        const uint32_t sA = sbase + st * STG;
        const __half* ab = g_a + (size_t)m0 * KH + k0;
        #pragma unroll
        for (int j = 0; j < 8; j++) {
            int id = tid + j * 128;
            int row = id >> 3, seg = id & 7;
            cp16(sA + sw128(row * 128 + seg * 16), ab + (size_t)row * KH + seg * 8);
        }
        const uint32_t sB = sA + A_STG;
        const __half* bb = g_w + (size_t)v0 * KH + k0;
        #pragma unroll
        for (int j = 0; j < 8; j++) {
            int id = tid + j * 128;
            int row = id >> 3, seg = id & 7;
            cp16(sB + sw128(row * 128 + seg * 16), bb + (size_t)row * KH + seg * 8);
        }
    };

    load_stage(0); cp_commit();
    load_stage(1); cp_commit();

    float acc[4][8][4];
    #pragma unroll
    for (int mt = 0; mt < 4; mt++)
        #pragma unroll
        for (int nt = 0; nt < 8; nt++)
            #pragma unroll
            for (int r = 0; r < 4; r++) acc[mt][nt][r] = 0.f;

    uint32_t aoff[4], boff[4];
    #pragma unroll
    for (int mt = 0; mt < 4; mt++)
        aoff[mt] = (uint32_t)(wm * 64 + mt * 16 + (lane & 7) + ((lane >> 3) & 1) * 8) * 128
                 + ((lane >> 4) & 1) * 16;
    #pragma unroll
    for (int np = 0; np < 4; np++)
        boff[np] = (uint32_t)(wn * 64 + np * 16 + ((lane >> 4) & 1) * 8 + (lane & 7)) * 128
                 + ((lane >> 3) & 1) * 16;

    for (int it = 0; it < NIT; ++it) {
        asm volatile("cp.async.wait_group 1;" ::: "memory");
        __syncthreads();

        const uint32_t sA = sbase + (it % NSTAGE) * STG;
        const uint32_t sB = sA + A_STG;
        const bool do_load = (it + 2 < NIT);
        const int lst = (it + 2) % NSTAGE;
        const uint32_t dA = sbase + lst * STG;
        const uint32_t dB = dA + A_STG;
        const int lk0 = (it + 2) * BK;
        const __half* ab = g_a + (size_t)m0 * KH + lk0;
        const __half* bb = g_w + (size_t)v0 * KH + lk0;

        #pragma unroll
        for (int ks = 0; ks < 4; ks++) {
            uint32_t a[4][4], b[4][4];
            #pragma unroll
            for (int mt = 0; mt < 4; mt++) ldsm4(a[mt], sA + sw128(aoff[mt] + ks * 32));
            #pragma unroll
            for (int np = 0; np < 4; np++) ldsm4(b[np], sB + sw128(boff[np] + ks * 32));

            if (do_load) {
                #pragma unroll
                for (int j = 0; j < 4; j++) {
                    const int chunk = ks * 4 + j;       // 0..15
                    const int id = tid + (chunk & 7) * 128;
                    const int row = id >> 3, seg = id & 7;
                    if (chunk < 8)
                        cp16(dA + sw128(row * 128 + seg * 16), ab + (size_t)row * KH + seg * 8);
                    else
                        cp16(dB + sw128(row * 128 + seg * 16), bb + (size_t)row * KH + seg * 8);
                }
            }

            #pragma unroll
            for (int mt = 0; mt < 4; mt++)
                #pragma unroll
                for (int nt = 0; nt < 8; nt++)
                    mma16816(acc[mt][nt], a[mt], b[nt >> 1] + (nt & 1) * 2);
        }
        cp_commit();
    }

    // ---------------- epilogue: f16x2 exp2 partial sums + target extract ----
    asm volatile("cp.async.wait_group 0;" ::: "memory");
    __syncthreads();
    uint32_t* sbias2 = reinterpret_cast<uint32_t*>(smem);          // 64 x half2
    int* stgt = reinterpret_cast<int*>(smem) + 64;                 // 128 x tgt col
    if (tid < 64) {
        __half2 h = __floats2half2_rn(bias[v0 + 2 * tid] * L2E,
                                      bias[v0 + 2 * tid + 1] * L2E);
        sbias2[tid] = *reinterpret_cast<uint32_t*>(&h);
    }
    {
        const int r = m0 + tid;
        stgt[tid] = (r < neff) ? (g_tgti[g_inv[r]] - v0) : 0x40000000;
    }
    __syncthreads();

    const int slice = vt * 2 + wn;
    const int pbase = wn * 32 + (lane & 3);          // half2 pair index of nt=0
    const int cbase = wn * 64 + (lane & 3) * 2;      // local col of reg j=0

    #pragma unroll
    for (int mt = 0; mt < 4; mt++) {
        #pragma unroll
        for (int half = 0; half < 2; half++) {
            const int row = wm * 64 + mt * 16 + (lane >> 2) + half * 8;
            const int ctok = m0 + row;               // compact token index
            uint32_t hs = 0;                         // half2 accumulator
            #pragma unroll
            for (int nt = 0; nt < 8; nt++) {
                uint32_t p = cvt_f16x2(acc[mt][nt][2 * half + 1], acc[mt][nt][2 * half]);
                p = hadd2u(p, sbias2[pbase + nt * 4]);
                hs = hadd2u(hs, ex2_f16x2(p));
            }
            const __half2 h = *reinterpret_cast<__half2*>(&hs);
            float S = __low2float(h) + __high2float(h);
            S += __shfl_xor_sync(0xffffffffu, S, 1);
            S += __shfl_xor_sync(0xffffffffu, S, 2);
            if ((lane & 3) == 0)
                g_psum[(size_t)slice * NTOK + ctok] = S;

            // target logit extraction via smem-cached column (rarely matches)
            const int tl = stgt[row] - cbase;
            if ((unsigned)tl < 58u) {                // only cols cbase..cbase+57 reachable
                #pragma unroll
                for (int nt = 0; nt < 8; nt++) {
                    if (tl == nt * 8)
                        g_tgt[g_inv[ctok]] = fmaf(acc[mt][nt][2 * half], LN2,
                                                  __ldg(&bias[v0 + cbase + nt * 8]));
                    if (tl == nt * 8 + 1)
                        g_tgt[g_inv[ctok]] = fmaf(acc[mt][nt][2 * half + 1], LN2,
                                                  __ldg(&bias[v0 + cbase + nt * 8 + 1]));
                }
            }
        }
    }

    // ---------------- tail: convert lookahead vtile's W (tensor-idle time) --
    if (cvt_vt < NVT) {
        convert_rows(wsrc4, cvt_vt, blockIdx.x, tid);
        __syncthreads();
        if (tid == 0) { __threadfence(); atomicAdd(&g_wcnt[cvt_vt], 1); }
    }
}

// ---------------- per-token combine: one warp per token --------------------
// 128 blocks x 512 threads = 2048 warps; each warp handles 2 tokens.
__global__ void __launch_bounds__(512) combine_kernel() {
    const int lane = threadIdx.x & 31;
    const int gwarp = blockIdx.x * 16 + (threadIdx.x >> 5);   // 0..2047
    #pragma unroll
    for (int half = 0; half < 2; half++) {
        const int token = gwarp + half * 2048;
        const int tg = g_tgti[token];
        float logp = 0.f;
        if (tg != -100) {
            const int c = g_cmap[token];
            float S = 0.f;
            const float* p = g_psum + c;
            #pragma unroll
            for (int k = 0; k < 16; k++) {           // 500 slices: lane + k*32 < 500
                const int sl = lane + k * 32;
                if (sl < NSLICE) S += p[(size_t)sl * NTOK];
            }
            #pragma unroll
            for (int o = 16; o > 0; o >>= 1) S += __shfl_xor_sync(0xffffffffu, S, o);
            logp = g_tgt[token] - __logf(S);
        }
        if (lane == 0) g_logp[token] = logp;
    }
}

// ---------------- per-sequence avg ----------------
__global__ void reduce_kernel() {
    __shared__ float rs[512];
    __shared__ float rc[512];
    const int seq = blockIdx.x, t = threadIdx.x;
    const int token = seq * 512 + t;
    const int masked = (g_tgti[token] == -100);
    rs[t] = masked ? 0.f : g_logp[token];
    rc[t] = masked ? 0.f : 1.f;
    __syncthreads();
    for (int o = 256; o > 0; o >>= 1) {
        if (t < o) { rs[t] += rs[t + o]; rc[t] += rc[t + o]; }
        __syncthreads();
    }
    if (t == 0) g_avg[seq] = rs[0] / fmaxf(rc[0], 1.f);
}

// ---------------- SimPO pair loss + counter reset for next replay ----------
__global__ void finalize_kernel(float* __restrict__ out) {
    for (int i = threadIdx.x; i < NVT; i += 32) g_wcnt[i] = 0;   // reset for replay
    if (threadIdx.x == 0 && blockIdx.x == 0) {
        float loss = 0.f;
        #pragma unroll
        for (int i = 0; i < 4; i++) {
            const float d = 0.1f * (g_avg[i] - g_avg[i + 4]) - 0.5f;
            const float xm = -d;  // -log_sigmoid(d) = softplus(-d)
            loss += (xm > 0.f) ? (xm + log1pf(expf(-xm))) : log1pf(expf(xm));
        }
        out[0] = loss * 0.25f;
    }
}

// ---------------- launch ----------------
extern "C" void kernel_launch(void* const* d_in, const int* in_sizes, int n_in,
                              void* d_out, int out_size) {
    const float* lin_weight = (const float*)d_in[0];       // [V, H]
    const float* input      = (const float*)d_in[1];       // [B, T, H]
    const int*   target_raw = (const int*)d_in[2];         // [B, T] int32 or int64
    const float* bias       = (const float*)d_in[3];       // [V]

    cudaFuncSetAttribute(gemm_softmax_kernel,
                         cudaFuncAttributeMaxDynamicSharedMemorySize, SMEM_BYTES);

    tgt_decode_kernel<<<1, 1024>>>(target_raw);
    cvt_w_pre_kernel<<<640, 256>>>((const float4*)lin_weight);  // vtiles 0..19
    cvt_a_kernel<<<NTOK, 256>>>(input);

    dim3 grid(NTOK / BM, NVT);   // x-fastest => M-CTAs share each W tile in L2
    gemm_softmax_kernel<<<grid, 128, SMEM_BYTES>>>(bias, lin_weight);

    combine_kernel<<<128, 512>>>();
    reduce_kernel<<<8, 512>>>();
    finalize_kernel<<<1, 32>>>((float*)d_out);
}

// round 17
// speedup vs baseline: 1.0733x; 1.0045x over previous
#include <cuda_runtime.h>
#include <cuda_fp16.h>
#include <cstdint>

// ---------------- problem constants ----------------
#define BM 128
#define BN 128
#define BK 64
#define KH 2048
#define NTOK 4096            // B*T
#define VSZ 32000
#define NVT (VSZ / BN)       // 250
#define NSLICE (NVT * 2)     // 500: each warp-n half writes its own partial
#define NIT (KH / BK)        // 32
#define NSTAGE 3
#define LOOKAHEAD 20         // vtile conversion lookahead (640 bids ~ 2+ waves)
#define L2E 1.44269504f      // log2(e)
#define LN2 0.69314718056f   // 1/log2(e)

// ---------------- device scratch (no allocs allowed) ----------------
__device__ __half g_w[(size_t)VSZ * KH];           // 128 MB fp16 weights
__device__ __half g_a[(size_t)NTOK * KH];          // 16 MB fp16 acts (compacted, x L2E)
__device__ float g_psum[(size_t)NSLICE * NTOK];    // per (slice, compact-token) sumexp
__device__ float g_tgt[NTOK];                      // target logit (fp32, orig idx)
__device__ float g_logp[NTOK];                     // per-token logp (orig idx)
__device__ int   g_tgti[NTOK];                     // decoded target indices (orig idx)
__device__ int   g_cmap[NTOK];                     // orig -> compact (-1 if masked)
__device__ int   g_inv[NTOK];                      // compact -> orig
__device__ int   g_neff[1];                        // number of unmasked tokens
__device__ int   g_wcnt[NVT];                      // per-vtile conversion counters (0-init)
__device__ float g_avg[8];                         // per-sequence avg logp

// ---------------- smem layout ----------------
#define A_STG (BM * 128)                 // 16384 B (128 rows x 128B)
#define B_STG (BN * 128)                 // 16384 B
#define STG   (A_STG + B_STG)            // 32768 B per stage
#define SMEM_BYTES (NSTAGE * STG)        // 98304 B -> 2 CTAs/SM

// ---------------- helpers ----------------
__device__ __forceinline__ uint32_t smem_u32(const void* p) {
    uint32_t a;
    asm("{ .reg .u64 t; cvta.to.shared.u64 t, %1; cvt.u32.u64 %0, t; }" : "=r"(a) : "l"(p));
    return a;
}
__device__ __forceinline__ uint32_t sw128(uint32_t off) { return off ^ ((off >> 3) & 0x70); }

__device__ __forceinline__ void cp16(uint32_t s, const void* g) {
    asm volatile("cp.async.cg.shared.global [%0], [%1], 16;" :: "r"(s), "l"(g) : "memory");
}
__device__ __forceinline__ void cp_commit() { asm volatile("cp.async.commit_group;" ::: "memory"); }

__device__ __forceinline__ void ldsm4(uint32_t* r, uint32_t addr) {
    asm volatile("ldmatrix.sync.aligned.m8n8.x4.shared.b16 {%0,%1,%2,%3}, [%4];"
                 : "=r"(r[0]), "=r"(r[1]), "=r"(r[2]), "=r"(r[3]) : "r"(addr));
}
__device__ __forceinline__ void mma16816(float* c, const uint32_t* a, const uint32_t* b) {
    asm volatile("mma.sync.aligned.m16n8k16.row.col.f32.f16.f16.f32 "
                 "{%0,%1,%2,%3}, {%4,%5,%6,%7}, {%8,%9}, {%0,%1,%2,%3};"
                 : "+f"(c[0]), "+f"(c[1]), "+f"(c[2]), "+f"(c[3])
                 : "r"(a[0]), "r"(a[1]), "r"(a[2]), "r"(a[3]), "r"(b[0]), "r"(b[1]));
}
__device__ __forceinline__ uint32_t cvt_f16x2(float hi, float lo) {
    uint32_t p;
    asm("cvt.rn.f16x2.f32 %0, %1, %2;" : "=r"(p) : "f"(hi), "f"(lo));
    return p;
}
__device__ __forceinline__ uint32_t hadd2u(uint32_t a, uint32_t b) {
    uint32_t d;
    asm("add.rn.f16x2 %0, %1, %2;" : "=r"(d) : "r"(a), "r"(b));
    return d;
}
__device__ __forceinline__ uint32_t ex2_f16x2(uint32_t a) {
    uint32_t d;
    asm("ex2.approx.f16x2 %0, %1;" : "=r"(d) : "r"(a));
    return d;
}
__device__ __forceinline__ int ld_acq(const int* p) {
    int v;
    asm volatile("ld.global.acquire.gpu.b32 %0, [%1];" : "=r"(v) : "l"(p) : "memory");
    return v;
}

// ---------------- decode + compaction (int32/int64 detect, prefix sum) ------
__global__ void __launch_bounds__(1024) tgt_decode_kernel(const int* __restrict__ t32) {
    __shared__ int s_is64;
    __shared__ int warp_tot[32];
    if (threadIdx.x == 0) s_is64 = 1;
    __syncthreads();
    int ok64 = 1;
    #pragma unroll
    for (int j = 0; j < 4; j++) {
        const int i = threadIdx.x + j * 1024;          // probe first 4096 words (16 KB, safe)
        const int v = t32[i];
        if (i & 1) { if (v != 0 && v != -1) ok64 = 0; }
        else       { if (!(v == -100 || (v >= 0 && v < VSZ))) ok64 = 0; }
    }
    if (!ok64) s_is64 = 0;
    __syncthreads();
    const int is64 = s_is64;

    int tg[4], msk[4], cnt = 0;
    #pragma unroll
    for (int j = 0; j < 4; j++) {
        const int i = threadIdx.x * 4 + j;
        tg[j] = is64 ? t32[2 * i] : t32[i];
        msk[j] = (tg[j] != -100);
        cnt += msk[j];
    }
    const int lane = threadIdx.x & 31, wid = threadIdx.x >> 5;
    int pre = cnt;
    #pragma unroll
    for (int o = 1; o < 32; o <<= 1) {
        int v = __shfl_up_sync(0xffffffffu, pre, o);
        if (lane >= o) pre += v;
    }
    if (lane == 31) warp_tot[wid] = pre;
    __syncthreads();
    if (wid == 0) {
        int v = warp_tot[lane];
        #pragma unroll
        for (int o = 1; o < 32; o <<= 1) {
            int u = __shfl_up_sync(0xffffffffu, v, o);
            if (lane >= o) v += u;
        }
        warp_tot[lane] = v;
    }
    __syncthreads();
    int base = (wid > 0 ? warp_tot[wid - 1] : 0) + (pre - cnt);
    #pragma unroll
    for (int j = 0; j < 4; j++) {
        const int i = threadIdx.x * 4 + j;
        g_tgti[i] = tg[j];
        if (msk[j]) { g_cmap[i] = base; g_inv[base] = i; base++; }
        else        { g_cmap[i] = -1; }
    }
    if (threadIdx.x == 1023) g_neff[0] = warp_tot[31];
}

// ---------------- fp32 -> fp16 converts ----------------
__device__ __forceinline__ unsigned pk2(float lo, float hi) {
    __half2 t = __floats2half2_rn(lo, hi);
    return *reinterpret_cast<unsigned*>(&t);
}
// pre-convert first LOOKAHEAD vtiles (rows 0..2559): 640 blocks x 256 thr.
__global__ void __launch_bounds__(256) cvt_w_pre_kernel(const float4* __restrict__ src) {
    const int p0 = blockIdx.x * 1024 + threadIdx.x;    // uint4 output index base
    float4 a[4], b[4];
    #pragma unroll
    for (int j = 0; j < 4; j++) {
        const int p = p0 + j * 256;
        a[j] = __ldcs(&src[2 * p]);
        b[j] = __ldcs(&src[2 * p + 1]);
    }
    #pragma unroll
    for (int j = 0; j < 4; j++) {
        const int p = p0 + j * 256;
        uint4 o;
        o.x = pk2(a[j].x, a[j].y); o.y = pk2(a[j].z, a[j].w);
        o.z = pk2(b[j].x, b[j].y); o.w = pk2(b[j].z, b[j].w);
        __stcs(reinterpret_cast<uint4*>(g_w) + p, o);
    }
}
// gather-compact + scale by log2(e): block = compact row
__global__ void __launch_bounds__(256) cvt_a_kernel(const float* __restrict__ src) {
    const int c = blockIdx.x;
    const int n = g_neff[0];
    uint4* dst = reinterpret_cast<uint4*>(g_a + (size_t)c * KH);
    if (c < n) {
        const int orig = g_inv[c];
        const float4* r4 = reinterpret_cast<const float4*>(src + (size_t)orig * KH);
        float4 a = __ldcs(&r4[2 * threadIdx.x]), b = __ldcs(&r4[2 * threadIdx.x + 1]);
        uint4 o;
        o.x = pk2(a.x * L2E, a.y * L2E); o.y = pk2(a.z * L2E, a.w * L2E);
        o.z = pk2(b.x * L2E, b.y * L2E); o.w = pk2(b.z * L2E, b.w * L2E);
        dst[threadIdx.x] = o;
    } else {
        dst[threadIdx.x] = make_uint4(0, 0, 0, 0);
    }
}

// convert 4 W rows of vtile cvt_vt (rows cvt_vt*128 + bx*4 .. +4) fp32->fp16
__device__ __forceinline__ void convert_rows(const float4* wsrc, int cvt_vt,
                                             int bx, int tid) {
    const int r0 = cvt_vt * BN + bx * 4;
    const float4* src = wsrc + (size_t)r0 * (KH / 4);
    uint4* dst = reinterpret_cast<uint4*>(g_w + (size_t)r0 * KH);
    #pragma unroll
    for (int batch = 0; batch < 2; batch++) {
        float4 a[4], b[4];
        #pragma unroll
        for (int j = 0; j < 4; j++) {
            const int p = tid + (batch * 4 + j) * 128;
            a[j] = __ldcs(&src[2 * p]);
            b[j] = __ldcs(&src[2 * p + 1]);
        }
        #pragma unroll
        for (int j = 0; j < 4; j++) {
            const int p = tid + (batch * 4 + j) * 128;
            uint4 o;
            o.x = pk2(a[j].x, a[j].y); o.y = pk2(a[j].z, a[j].w);
            o.z = pk2(b[j].x, b[j].y); o.w = pk2(b[j].z, b[j].w);
            __stcs(dst + p, o);
        }
    }
}

// ---------------- fused GEMM + partial sum-exp + target + W-pipeline --------
// acc = log2(e) * logit_nobias (A pre-scaled by L2E).
// Block (bx, vt): issues A-prologue cp.asyncs, converts 4 rows of vtile
// vt+LOOKAHEAD (head position: overlaps A loads), signals, waits for vtile
// vt's W (converted by blocks of vt-LOOKAHEAD), then GEMM+softmax.
__global__ void __launch_bounds__(128, 2) gemm_softmax_kernel(
    const float* __restrict__ bias, const float* __restrict__ wsrc) {
    const int neff = g_neff[0];
    const int m0 = blockIdx.x * BM;
    const int vt = blockIdx.y;
    const int v0 = vt * BN;
    const int cvt_vt = vt + LOOKAHEAD;
    const int tid = threadIdx.x;
    const float4* wsrc4 = reinterpret_cast<const float4*>(wsrc);

    if (m0 >= neff) {                                // masked tile: convert + signal + exit
        if (cvt_vt < NVT) {
            convert_rows(wsrc4, cvt_vt, blockIdx.x, tid);
            __syncthreads();
            if (tid == 0) { __threadfence(); atomicAdd(&g_wcnt[cvt_vt], 1); }
        }
        return;
    }

    extern __shared__ char smem[];
    const uint32_t sbase = smem_u32(smem);
    const int lane = tid & 31;
    const int warp = tid >> 5;
    const int wm = warp >> 1;          // 0..1  (m slice of 64 rows)
    const int wn = warp & 1;           // 0..1  (n slice of 64 cols)

    auto load_stage_a = [&](int it) {
        const int st = it % NSTAGE;
        const uint32_t sA = sbase + st * STG;
        const __half* ab = g_a + (size_t)m0 * KH + it * BK;
        #pragma unroll
        for (int j = 0; j < 8; j++) {
            int id = tid + j * 128;
            int row = id >> 3, seg = id & 7;
            cp16(sA + sw128(row * 128 + seg * 16), ab + (size_t)row * KH + seg * 8);
        }
    };
    auto load_stage_b = [&](int it) {
        const int st = it % NSTAGE;
        const uint32_t sB = sbase + st * STG + A_STG;
        const __half* bb = g_w + (size_t)v0 * KH + it * BK;
        #pragma unroll
        for (int j = 0; j < 8; j++) {
            int id = tid + j * 128;
            int row = id >> 3, seg = id & 7;
            cp16(sB + sw128(row * 128 + seg * 16), bb + (size_t)row * KH + seg * 8);
        }
    };

    // ---- A prologue (independent of W) overlaps the conversion below ----
    load_stage_a(0);
    load_stage_a(1);

    // ---- convert lookahead vtile's W rows (head position) ----
    if (cvt_vt < NVT) {
        convert_rows(wsrc4, cvt_vt, blockIdx.x, tid);
        __syncthreads();
        if (tid == 0) { __threadfence(); atomicAdd(&g_wcnt[cvt_vt], 1); }
    }

    // ---- wait until this vtile's W is fully converted ----
    if (vt >= LOOKAHEAD) {
        if (tid == 0) {
            while (ld_acq(&g_wcnt[vt]) < 32) { __nanosleep(32); }
        }
        __syncthreads();
    }

    // ---- B prologue; group g0 = {A0, A1, B0}, g1 = {B1} ----
    load_stage_b(0); cp_commit();
    load_stage_b(1); cp_commit();

    float acc[4][8][4];
    #pragma unroll
    for (int mt = 0; mt < 4; mt++)
        #pragma unroll
        for (int nt = 0; nt < 8; nt++)
            #pragma unroll
            for (int r = 0; r < 4; r++) acc[mt][nt][r] = 0.f;

    uint32_t aoff[4], boff[4];
    #pragma unroll
    for (int mt = 0; mt < 4; mt++)
        aoff[mt] = (uint32_t)(wm * 64 + mt * 16 + (lane & 7) + ((lane >> 3) & 1) * 8) * 128
                 + ((lane >> 4) & 1) * 16;
    #pragma unroll
    for (int np = 0; np < 4; np++)
        boff[np] = (uint32_t)(wn * 64 + np * 16 + ((lane >> 4) & 1) * 8 + (lane & 7)) * 128
                 + ((lane >> 3) & 1) * 16;

    for (int it = 0; it < NIT; ++it) {
        asm volatile("cp.async.wait_group 1;" ::: "memory");
        __syncthreads();

        const uint32_t sA = sbase + (it % NSTAGE) * STG;
        const uint32_t sB = sA + A_STG;
        const bool do_load = (it + 2 < NIT);
        const int lst = (it + 2) % NSTAGE;
        const uint32_t dA = sbase + lst * STG;
        const uint32_t dB = dA + A_STG;
        const int lk0 = (it + 2) * BK;
        const __half* ab = g_a + (size_t)m0 * KH + lk0;
        const __half* bb = g_w + (size_t)v0 * KH + lk0;

        #pragma unroll
        for (int ks = 0; ks < 4; ks++) {
            uint32_t a[4][4], b[4][4];
            #pragma unroll
            for (int mt = 0; mt < 4; mt++) ldsm4(a[mt], sA + sw128(aoff[mt] + ks * 32));
            #pragma unroll
            for (int np = 0; np < 4; np++) ldsm4(b[np], sB + sw128(boff[np] + ks * 32));

            if (do_load) {
                #pragma unroll
                for (int j = 0; j < 4; j++) {
                    const int chunk = ks * 4 + j;       // 0..15
                    const int id = tid + (chunk & 7) * 128;
                    const int row = id >> 3, seg = id & 7;
                    if (chunk < 8)
                        cp16(dA + sw128(row * 128 + seg * 16), ab + (size_t)row * KH + seg * 8);
                    else
                        cp16(dB + sw128(row * 128 + seg * 16), bb + (size_t)row * KH + seg * 8);
                }
            }

            #pragma unroll
            for (int mt = 0; mt < 4; mt++)
                #pragma unroll
                for (int nt = 0; nt < 8; nt++)
                    mma16816(acc[mt][nt], a[mt], b[nt >> 1] + (nt & 1) * 2);
        }
        cp_commit();
    }

    // ---------------- epilogue: f16x2 exp2 partial sums + target extract ----
    asm volatile("cp.async.wait_group 0;" ::: "memory");
    __syncthreads();
    uint32_t* sbias2 = reinterpret_cast<uint32_t*>(smem);          // 64 x half2
    int* stgt = reinterpret_cast<int*>(smem) + 64;                 // 128 x tgt col
    if (tid < 64) {
        __half2 h = __floats2half2_rn(bias[v0 + 2 * tid] * L2E,
                                      bias[v0 + 2 * tid + 1] * L2E);
        sbias2[tid] = *reinterpret_cast<uint32_t*>(&h);
    }
    {
        const int r = m0 + tid;
        stgt[tid] = (r < neff) ? (g_tgti[g_inv[r]] - v0) : 0x40000000;
    }
    __syncthreads();

    const int slice = vt * 2 + wn;
    const int pbase = wn * 32 + (lane & 3);          // half2 pair index of nt=0
    const int cbase = wn * 64 + (lane & 3) * 2;      // local col of reg j=0

    #pragma unroll
    for (int mt = 0; mt < 4; mt++) {
        #pragma unroll
        for (int half = 0; half < 2; half++) {
            const int row = wm * 64 + mt * 16 + (lane >> 2) + half * 8;
            const int ctok = m0 + row;               // compact token index
            uint32_t hs = 0;                         // half2 accumulator
            #pragma unroll
            for (int nt = 0; nt < 8; nt++) {
                uint32_t p = cvt_f16x2(acc[mt][nt][2 * half + 1], acc[mt][nt][2 * half]);
                p = hadd2u(p, sbias2[pbase + nt * 4]);
                hs = hadd2u(hs, ex2_f16x2(p));
            }
            const __half2 h = *reinterpret_cast<__half2*>(&hs);
            float S = __low2float(h) + __high2float(h);
            S += __shfl_xor_sync(0xffffffffu, S, 1);
            S += __shfl_xor_sync(0xffffffffu, S, 2);
            if ((lane & 3) == 0)
                g_psum[(size_t)slice * NTOK + ctok] = S;

            // target logit extraction via smem-cached column (rarely matches)
            const int tl = stgt[row] - cbase;
            if ((unsigned)tl < 58u) {                // only cols cbase..cbase+57 reachable
                #pragma unroll
                for (int nt = 0; nt < 8; nt++) {
                    if (tl == nt * 8)
                        g_tgt[g_inv[ctok]] = fmaf(acc[mt][nt][2 * half], LN2,
                                                  __ldg(&bias[v0 + cbase + nt * 8]));
                    if (tl == nt * 8 + 1)
                        g_tgt[g_inv[ctok]] = fmaf(acc[mt][nt][2 * half + 1], LN2,
                                                  __ldg(&bias[v0 + cbase + nt * 8 + 1]));
                }
            }
        }
    }
}

// ---------------- per-token combine: one warp per token --------------------
// 128 blocks x 512 threads = 2048 warps; each warp handles 2 tokens.
__global__ void __launch_bounds__(512) combine_kernel() {
    const int lane = threadIdx.x & 31;
    const int gwarp = blockIdx.x * 16 + (threadIdx.x >> 5);   // 0..2047
    #pragma unroll
    for (int half = 0; half < 2; half++) {
        const int token = gwarp + half * 2048;
        const int tg = g_tgti[token];
        float logp = 0.f;
        if (tg != -100) {
            const int c = g_cmap[token];
            float S = 0.f;
            const float* p = g_psum + c;
            #pragma unroll
            for (int k = 0; k < 16; k++) {           // 500 slices: lane + k*32 < 500
                const int sl = lane + k * 32;
                if (sl < NSLICE) S += p[(size_t)sl * NTOK];
            }
            #pragma unroll
            for (int o = 16; o > 0; o >>= 1) S += __shfl_xor_sync(0xffffffffu, S, o);
            logp = g_tgt[token] - __logf(S);
        }
        if (lane == 0) g_logp[token] = logp;
    }
}

// ---------------- per-sequence avg ----------------
__global__ void reduce_kernel() {
    __shared__ float rs[512];
    __shared__ float rc[512];
    const int seq = blockIdx.x, t = threadIdx.x;
    const int token = seq * 512 + t;
    const int masked = (g_tgti[token] == -100);
    rs[t] = masked ? 0.f : g_logp[token];
    rc[t] = masked ? 0.f : 1.f;
    __syncthreads();
    for (int o = 256; o > 0; o >>= 1) {
        if (t < o) { rs[t] += rs[t + o]; rc[t] += rc[t + o]; }
        __syncthreads();
    }
    if (t == 0) g_avg[seq] = rs[0] / fmaxf(rc[0], 1.f);
}

// ---------------- SimPO pair loss + counter reset for next replay ----------
__global__ void finalize_kernel(float* __restrict__ out) {
    for (int i = threadIdx.x; i < NVT; i += 32) g_wcnt[i] = 0;   // reset for replay
    if (threadIdx.x == 0 && blockIdx.x == 0) {
        float loss = 0.f;
        #pragma unroll
        for (int i = 0; i < 4; i++) {
            const float d = 0.1f * (g_avg[i] - g_avg[i + 4]) - 0.5f;
            const float xm = -d;  // -log_sigmoid(d) = softplus(-d)
            loss += (xm > 0.f) ? (xm + log1pf(expf(-xm))) : log1pf(expf(xm));
        }
        out[0] = loss * 0.25f;
    }
}

// ---------------- launch ----------------
extern "C" void kernel_launch(void* const* d_in, const int* in_sizes, int n_in,
                              void* d_out, int out_size) {
    const float* lin_weight = (const float*)d_in[0];       // [V, H]
    const float* input      = (const float*)d_in[1];       // [B, T, H]
    const int*   target_raw = (const int*)d_in[2];         // [B, T] int32 or int64
    const float* bias       = (const float*)d_in[3];       // [V]

    cudaFuncSetAttribute(gemm_softmax_kernel,
                         cudaFuncAttributeMaxDynamicSharedMemorySize, SMEM_BYTES);

    tgt_decode_kernel<<<1, 1024>>>(target_raw);
    cvt_w_pre_kernel<<<640, 256>>>((const float4*)lin_weight);  // vtiles 0..19
    cvt_a_kernel<<<NTOK, 256>>>(input);

    dim3 grid(NTOK / BM, NVT);   // x-fastest => M-CTAs share each W tile in L2
    gemm_softmax_kernel<<<grid, 128, SMEM_BYTES>>>(bias, lin_weight);

    combine_kernel<<<128, 512>>>();
    reduce_kernel<<<8, 512>>>();
    finalize_kernel<<<1, 32>>>((float*)d_out);
}